// round 16
// baseline (speedup 1.0000x reference)
#include <cuda_runtime.h>
#include <math.h>

#define NB_MOL 128
#define NA 512
#define NF 64
#define CO 14.399645478425668f
#define SQRT_PI 1.7724538509055159f
#define PS 480

typedef unsigned long long u64;

// ---------------- scratch (device globals; no allocation allowed) ----------
__device__ float g_C[(size_t)NB_MOL * NA * NA];   // matrix / Cholesky factor (lower)

// ---------------- packed fp32x2 helpers (sm_103a FFMA2 path) ---------------
__device__ __forceinline__ void ffma2(u64& acc, u64 a, u64 b) {
    asm("fma.rn.f32x2 %0, %1, %2, %0;" : "+l"(acc) : "l"(a), "l"(b));
}
__device__ __forceinline__ u64 fmul2(u64 a, u64 b) {
    u64 r; asm("mul.rn.f32x2 %0, %1, %2;" : "=l"(r) : "l"(a), "l"(b)); return r;
}
__device__ __forceinline__ u64 fadd2(u64 a, u64 b) {
    u64 r; asm("add.rn.f32x2 %0, %1, %2;" : "=l"(r) : "l"(a), "l"(b)); return r;
}
__device__ __forceinline__ u64 splat2(float x) {
    u64 r; asm("mov.b64 %0, {%1, %1};" : "=l"(r) : "f"(x)); return r;
}
__device__ __forceinline__ u64 nsplat2(float x) {
    float nx = -x;
    u64 r; asm("mov.b64 %0, {%1, %1};" : "=l"(r) : "f"(nx)); return r;
}
__device__ __forceinline__ u64 pack2(float lo, float hi) {
    u64 r; asm("mov.b64 %0, {%1, %2};" : "=l"(r) : "f"(lo), "f"(hi)); return r;
}
__device__ __forceinline__ void unpack2(u64 v, float& lo, float& hi) {
    asm("mov.b64 {%0, %1}, %2;" : "=f"(lo), "=f"(hi) : "l"(v));
}

// ---------------- build C, LOWER TRIANGLE ONLY (pair table + erf sat) ------
__global__ void __launch_bounds__(256) build_kernel(const float* __restrict__ pos,
                                                    const int*   __restrict__ atype,
                                                    const float* __restrict__ hard,
                                                    const float* __restrict__ sigma) {
    __shared__ float sx[NA], sy[NA], sz[NA], sdg[NA];
    __shared__ int   st[NA];
    __shared__ float prg[16], prg2[16];
    int m   = blockIdx.y;
    int rb  = blockIdx.x * 32;
    int tid = threadIdx.x;
    for (int i = tid; i < NA; i += 256) {
        int g = m * NA + i;
        sx[i] = pos[3 * g];  sy[i] = pos[3 * g + 1];  sz[i] = pos[3 * g + 2];
        int sp = atype[g];
        st[i] = sp;
        float sg = sigma[sp];
        sdg[i] = hard[sp] * hard[sp] + CO / (SQRT_PI * sg);
    }
    if (tid < 16) {
        float sa = sigma[tid >> 2], sb = sigma[tid & 3];
        float rg = rsqrtf(2.f * (sa * sa + sb * sb));
        prg[tid]  = rg;
        prg2[tid] = rg * rg;
    }
    __syncthreads();
    float* C = g_C + (size_t)m * NA * NA;
    int ncol = rb + 32;
    for (int il = 0; il < 32; ++il) {
        int i = rb + il;
        float xi = sx[i], yi = sy[i], zi = sz[i];
        int   ti4 = st[i] * 4;
        for (int j = tid; j < ncol; j += 256) {
            float val;
            if (j == i) {
                val = sdg[i];
            } else {
                float dx = xi - sx[j], dy = yi - sy[j], dz = zi - sz[j];
                float d2 = dx * dx + dy * dy + dz * dz;
                float rd = rsqrtf(d2);
                int   pi = ti4 + st[j];
                float t2 = d2 * prg2[pi];
                if (t2 > 16.0f)
                    val = CO * rd;                              // erf saturated to 1
                else
                    val = CO * erff(d2 * rd * prg[pi]) * rd;
            }
            C[(size_t)i * NA + j] = val;
        }
    }
}

// ------- fused: chi + paired-panel Cholesky + fwd/bwd solve + outputs ------
// shared layout (float offsets)
#define SH_PT0    0                      // [32][PS] panel of even sub-block
#define SH_PT1    (32 * PS)              // [32][PS] panel of odd  sub-block
#define SH_D      (2 * 32 * PS)          // 2 x [32][33] ping-pong diag
#define SH_DT     (SH_D + 2 * 32 * 33)   // [32][34] transposed diag (u64-aligned)
#define SH_INV    (SH_DT + 32 * 34)      // [32]
#define SH_INVP2  (SH_INV + 32)          // [32] u64 pairs  (even float offset)
#define SH_INVALL (SH_INVP2 + 64)        // [512]
#define SH_BP     (SH_INVALL + 512)      // [512] u64 pairs (even float offset)
#define SH_CHI    (SH_BP + 1024)         // [512]
#define SH_RED    (SH_CHI + 512)         // [64]
#define SH_LAM    (SH_RED + 64)          // [1]
#define CHO_SHMEM ((SH_LAM + 4) * 4)

extern __shared__ float cho_sh[];

__global__ void __launch_bounds__(512) fact_solve_kernel(const float* __restrict__ feats,
                                                         const float* __restrict__ wv,
                                                         const float* __restrict__ tc,
                                                         float* __restrict__ out) {
    float* s_Pt0    = cho_sh + SH_PT0;
    float* s_Pt1    = cho_sh + SH_PT1;
    float* s_Dbuf   = cho_sh + SH_D;
    float* s_DT     = cho_sh + SH_DT;
    float* s_inv    = cho_sh + SH_INV;
    u64*   s_invp2  = (u64*)(cho_sh + SH_INVP2);
    float* s_invall = cho_sh + SH_INVALL;
    u64*   s_bp     = (u64*)(cho_sh + SH_BP);
    float* s_chi    = cho_sh + SH_CHI;
    float* s_red    = cho_sh + SH_RED;
    float* s_lam    = cho_sh + SH_LAM;

    int m    = blockIdx.x;
    float* C = g_C + (size_t)m * NA * NA;
    int tid = threadIdx.x, lane = tid & 31, wid = tid >> 5;

    // ---- prologue: chi = feats @ w (per-warp shuffle reduce) ----
    {
        float w0 = wv[lane], w1 = wv[lane + 32];
        for (int a = wid; a < NA; a += 16) {
            const float* fr = feats + (size_t)(m * NA + a) * NF;
            float v = fr[lane] * w0 + fr[lane + 32] * w1;
#pragma unroll
            for (int off = 16; off; off >>= 1) v += __shfl_down_sync(0xffffffffu, v, off);
            if (lane == 0) s_chi[a] = v;
        }
    }
    __syncthreads();
    // rhs pairs: (b0, b1) = (-chi, 1); also load diag(0) into buffer 0
    s_bp[tid] = pack2(-s_chi[tid], 1.0f);
    for (int t = tid; t < 1024; t += 512) {
        int i = t >> 5, j = t & 31;
        s_Dbuf[i * 33 + j] = C[(size_t)i * NA + j];
    }
    __syncthreads();

    // =================== factorization + forward substitution ==============
    for (int kb = 0; kb < NA / 32; ++kb) {
        int k0 = kb * 32;
        int M  = NA - k0 - 32;
        bool even = ((kb & 1) == 0);
        float* s_P  = even ? s_Pt0 : s_Pt1;
        float* s_Dc = s_Dbuf + (kb & 1) * (32 * 33);
        float* s_Dn = s_Dbuf + ((kb + 1) & 1) * (32 * 33);

        // ---- B: warp0 register-factor of diag; threads 32.. prefetch ----
        float a[32];          // warp0: its row of the diag factor (live thru D)
        float iv_own = 0.f;   // warp0: 1/L[lane][lane]
        u64 ap[16];
        int r = tid - 32;
        bool havrow = (tid >= 32) && (r < M);
        if (wid == 0) {
#pragma unroll
            for (int j = 0; j < 32; ++j) a[j] = s_Dc[lane * 33 + j];
#pragma unroll
            for (int k = 0; k < 32; ++k) {
                float d  = __shfl_sync(0xffffffffu, a[k], k);
                float iv = rsqrtf(d);
                if (lane == k) iv_own = iv;
                if (lane >= k) a[k] *= iv;       // lane k: d*iv = sqrt(d)
                float xk = a[k];
#pragma unroll
                for (int i = k + 1; i < 32; ++i) {
                    float vi = __shfl_sync(0xffffffffu, xk, i);
                    if (lane >= i) a[i] -= xk * vi;
                }
            }
            s_inv[lane]         = iv_own;
            s_invall[k0 + lane] = iv_own;
            s_invp2[lane] = (lane & 1) ? pack2(1.0f, iv_own)
                                       : pack2(iv_own, 1.0f);
#pragma unroll
            for (int t = 0; t < 32; ++t) s_DT[t * 34 + lane] = a[t];  // s_DT[t][j]=L[j][t]
        } else if (havrow) {
            const double2* rp = (const double2*)(C + (size_t)(k0 + 32 + r) * NA + k0);
#pragma unroll
            for (int c = 0; c < 8; ++c) {
                double2 v = rp[c];
                ap[2 * c]     = __double_as_longlong(v.x);
                ap[2 * c + 1] = __double_as_longlong(v.y);
            }
        }
        __syncthreads();

        // ---- C: warp0 writes diag to C from regs; panel threads trsm ----
        if (wid == 0) {
#pragma unroll
            for (int jc = 0; jc < 8; ++jc)
                *(float4*)(C + (size_t)(k0 + lane) * NA + k0 + 4 * jc) =
                    make_float4(a[4 * jc], a[4 * jc + 1], a[4 * jc + 2], a[4 * jc + 3]);
        } else if (havrow) {
#pragma unroll
            for (int t = 0; t < 32; ++t) {
                int tp = t >> 1;
                ap[tp] = fmul2(ap[tp], s_invp2[t]);           // scale element t only
                float xlo, xhi;
                unpack2(ap[tp], xlo, xhi);
                float xv = (t & 1) ? xhi : xlo;
                if ((t & 1) == 0) {                            // partner j = t+1 in same pair
                    u64 p = *(const u64*)(s_DT + t * 34 + t);  // (L[t][t], L[t+1][t])
                    ffma2(ap[tp], pack2(0.0f, -xv), p);
                }
                u64 nx = nsplat2(xv);
#pragma unroll
                for (int jp = tp + 1; jp < 16; ++jp)
                    ffma2(ap[jp], nx, *(const u64*)(s_DT + t * 34 + 2 * jp));
            }
            double2* wp = (double2*)(C + (size_t)(k0 + 32 + r) * NA + k0);
#pragma unroll
            for (int c = 0; c < 8; ++c)
                wp[c] = make_double2(__longlong_as_double(ap[2 * c]),
                                     __longlong_as_double(ap[2 * c + 1]));
#pragma unroll
            for (int tp = 0; tp < 16; ++tp) {
                float lo, hi;
                unpack2(ap[tp], lo, hi);
                s_P[(2 * tp) * PS + r]     = lo;               // transposed panel
                s_P[(2 * tp + 1) * PS + r] = hi;
            }
        }
        __syncthreads();

        // ---- D: warp0 solver (register L); warps 1-15 SYRK/skinny ----
        if (wid == 0) {
            // z-block solve: L11 z = b (both RHS packed); L from registers
            u64 av = s_bp[k0 + lane];
#pragma unroll
            for (int t = 0; t < 32; ++t) {
                u64 vt   = __shfl_sync(0xffffffffu, av, t);
                float it = __shfl_sync(0xffffffffu, iv_own, t);
                u64 v    = fmul2(vt, splat2(it));
                if (lane == t) s_bp[k0 + t] = v;
                if (lane > t) ffma2(av, nsplat2(a[t]), v);
            }
            __syncwarp();
            // trailing b -= L21 * z (panel in shared)
            for (int rr = lane; rr < M; rr += 32) {
                u64 bp = s_bp[k0 + 32 + rr];
#pragma unroll 8
                for (int t = 0; t < 32; ++t)
                    ffma2(bp, nsplat2(s_P[t * PS + rr]), s_bp[k0 + t]);
                s_bp[k0 + 32 + rr] = bp;
            }
        } else if (M > 0) {
            if (even) {
                // skinny update: next 32-col strip only (rank 32); static map
                int bi = wid - 1;
                if (bi * 32 < M) {
                    int rr = bi * 32 + lane;
                    u64 acc[16];
#pragma unroll
                    for (int c = 0; c < 16; ++c) acc[c] = 0ull;
#pragma unroll 8
                    for (int t = 0; t < 32; ++t) {
                        u64 na = nsplat2(s_P[t * PS + rr]);
                        const double2* pp = (const double2*)(s_P + t * PS);
#pragma unroll
                        for (int c = 0; c < 8; ++c) {
                            double2 p = pp[c];
                            ffma2(acc[2 * c],     na, __double_as_longlong(p.x));
                            ffma2(acc[2 * c + 1], na, __double_as_longlong(p.y));
                        }
                    }
                    double2* cp = (double2*)(C + (size_t)(k0 + 32 + rr) * NA + k0 + 32);
#pragma unroll
                    for (int c = 0; c < 8; ++c) {
                        double2 v = cp[c];
                        u64 vx = fadd2(__double_as_longlong(v.x), acc[2 * c]);
                        u64 vy = fadd2(__double_as_longlong(v.y), acc[2 * c + 1]);
                        v.x = __longlong_as_double(vx);
                        v.y = __longlong_as_double(vy);
                        cp[c] = v;
                        if (bi == 0) {                         // mirror next diag
                            float f0, f1, f2, f3;
                            unpack2(vx, f0, f1); unpack2(vy, f2, f3);
                            s_Dn[lane * 33 + 4 * c]     = f0;
                            s_Dn[lane * 33 + 4 * c + 1] = f1;
                            s_Dn[lane * 33 + 4 * c + 2] = f2;
                            s_Dn[lane * 33 + 4 * c + 3] = f3;
                        }
                    }
                }
            } else {
                // rank-64 trailing SYRK (64x32 tiles); static round-robin map
                int wslot = wid - 1;
                int RT = (M + 63) >> 6;
                int CT = M >> 5;
                int cnt = 0;
                for (int bi = 0; bi < RT; ++bi) {
                    int bjmax = min(2 * bi + 1, CT - 1);
                    for (int bj = 0; bj <= bjmax; ++bj) {
                        if (cnt == wslot) {
                            int r1 = bi * 64 + lane, r2 = r1 + 32;
                            int cb = bj * 32;
                            u64 acc0[16], acc1[16];
#pragma unroll
                            for (int c = 0; c < 16; ++c) { acc0[c] = 0ull; acc1[c] = 0ull; }
                            // panel 1 (current odd block)
#pragma unroll 8
                            for (int t = 0; t < 32; ++t) {
                                u64 na0 = nsplat2(s_Pt1[t * PS + r1]);
                                u64 na1 = nsplat2(s_Pt1[t * PS + r2]);
                                const double2* pp = (const double2*)(s_Pt1 + t * PS + cb);
#pragma unroll
                                for (int c = 0; c < 8; ++c) {
                                    double2 p = pp[c];
                                    u64 pl = __double_as_longlong(p.x);
                                    u64 ph = __double_as_longlong(p.y);
                                    ffma2(acc0[2 * c],     na0, pl);
                                    ffma2(acc0[2 * c + 1], na0, ph);
                                    ffma2(acc1[2 * c],     na1, pl);
                                    ffma2(acc1[2 * c + 1], na1, ph);
                                }
                            }
                            // panel 0 (previous even block; rows shifted by 32)
#pragma unroll 8
                            for (int t = 0; t < 32; ++t) {
                                u64 na0 = nsplat2(s_Pt0[t * PS + r1 + 32]);
                                u64 na1 = nsplat2(s_Pt0[t * PS + r2 + 32]);
                                const double2* pp = (const double2*)(s_Pt0 + t * PS + cb + 32);
#pragma unroll
                                for (int c = 0; c < 8; ++c) {
                                    double2 p = pp[c];
                                    u64 pl = __double_as_longlong(p.x);
                                    u64 ph = __double_as_longlong(p.y);
                                    ffma2(acc0[2 * c],     na0, pl);
                                    ffma2(acc0[2 * c + 1], na0, ph);
                                    ffma2(acc1[2 * c],     na1, pl);
                                    ffma2(acc1[2 * c + 1], na1, ph);
                                }
                            }
                            {
                                double2* cp = (double2*)(C + (size_t)(k0 + 32 + r1) * NA + k0 + 32 + cb);
                                bool mir = (bi == 0) && (bj == 0);
#pragma unroll
                                for (int c = 0; c < 8; ++c) {
                                    double2 v = cp[c];
                                    u64 vx = fadd2(__double_as_longlong(v.x), acc0[2 * c]);
                                    u64 vy = fadd2(__double_as_longlong(v.y), acc0[2 * c + 1]);
                                    v.x = __longlong_as_double(vx);
                                    v.y = __longlong_as_double(vy);
                                    cp[c] = v;
                                    if (mir) {                  // mirror next diag
                                        float f0, f1, f2, f3;
                                        unpack2(vx, f0, f1); unpack2(vy, f2, f3);
                                        s_Dn[lane * 33 + 4 * c]     = f0;
                                        s_Dn[lane * 33 + 4 * c + 1] = f1;
                                        s_Dn[lane * 33 + 4 * c + 2] = f2;
                                        s_Dn[lane * 33 + 4 * c + 3] = f3;
                                    }
                                }
                            }
                            {
                                double2* cp = (double2*)(C + (size_t)(k0 + 32 + r2) * NA + k0 + 32 + cb);
#pragma unroll
                                for (int c = 0; c < 8; ++c) {
                                    double2 v = cp[c];
                                    v.x = __longlong_as_double(fadd2(__double_as_longlong(v.x), acc1[2 * c]));
                                    v.y = __longlong_as_double(fadd2(__double_as_longlong(v.y), acc1[2 * c + 1]));
                                    cp[c] = v;
                                }
                            }
                        }
                        if (++cnt == 15) cnt = 0;
                    }
                }
            }
        }
        __syncthreads();
    }

    // =================== backward: L^T y = z ================================
    float* s_D = s_Dbuf;   // reuse buffer 0
    for (int kb = NA / 32 - 1; kb >= 0; --kb) {
        int k0 = kb * 32;
        if (wid == 0) {
            for (int e = lane; e < 1024; e += 32) {
                int i = e >> 5, j = e & 31;
                s_D[i * 33 + j] = C[(size_t)(k0 + i) * NA + k0 + j];
            }
            __syncwarp();
            u64 av = s_bp[k0 + lane];
            for (int t = 31; t >= 0; --t) {
                u64 vt = __shfl_sync(0xffffffffu, av, t);
                u64 v  = fmul2(vt, splat2(s_invall[k0 + t]));
                if (lane == t) s_bp[k0 + t] = v;
                float l = s_D[t * 33 + lane];
                if (lane < t) ffma2(av, nsplat2(l), v);
            }
        }
        __syncthreads();
        for (int j = tid; j < k0; j += 512) {
            u64 bp = s_bp[j];
#pragma unroll
            for (int t = 0; t < 32; ++t)
                ffma2(bp, nsplat2(C[(size_t)(k0 + t) * NA + j]), s_bp[k0 + t]);
            s_bp[j] = bp;
        }
        __syncthreads();
    }

    // =================== lambda, q, energy ==================================
    float y0, y1;
    unpack2(s_bp[tid], y0, y1);
    float l0 = y0, l1 = y1;
#pragma unroll
    for (int off = 16; off; off >>= 1) {
        l0 += __shfl_down_sync(0xffffffffu, l0, off);
        l1 += __shfl_down_sync(0xffffffffu, l1, off);
    }
    if (lane == 0) { s_red[wid] = l0; s_red[32 + wid] = l1; }
    __syncthreads();
    if (tid == 0) {
        float S1 = 0.f, S2 = 0.f;
        for (int w = 0; w < 16; ++w) { S1 += s_red[w]; S2 += s_red[32 + w]; }
        *s_lam = (S1 - tc[m]) / S2;
    }
    __syncthreads();
    float lam = *s_lam;

    float q = y0 - lam * y1;
    out[NB_MOL + m * NA + tid] = q;

    // e = 0.5 * (chi.q - lam * Q)   [exact KKT identity]
    float ep = s_chi[tid] * q;
#pragma unroll
    for (int off = 16; off; off >>= 1) ep += __shfl_down_sync(0xffffffffu, ep, off);
    if (lane == 0) s_red[wid] = ep;
    __syncthreads();
    if (tid == 0) {
        float s = 0.f;
        for (int w = 0; w < 16; ++w) s += s_red[w];
        out[m] = 0.5f * (s - lam * tc[m]);
    }
}

// ---------------- launch ----------------------------------------------------
extern "C" void kernel_launch(void* const* d_in, const int* in_sizes, int n_in,
                              void* d_out, int out_size) {
    const float* feats = (const float*)d_in[0];   // (N, 64)
    const float* pos   = (const float*)d_in[1];   // (N, 3)
    const int*   atype = (const int*)  d_in[2];   // (N,)
    const float* tc    = (const float*)d_in[3];   // (B, 1)
    const float* w     = (const float*)d_in[4];   // (64, 1)
    const float* hard  = (const float*)d_in[5];   // (4,)
    const float* sigma = (const float*)d_in[6];   // (4,)
    float* out = (float*)d_out;                   // [B e | N q]

    (void)in_sizes; (void)n_in; (void)out_size;

    build_kernel<<<dim3(16, NB_MOL), 256>>>(pos, atype, hard, sigma);
    cudaFuncSetAttribute(fact_solve_kernel, cudaFuncAttributeMaxDynamicSharedMemorySize, CHO_SHMEM);
    fact_solve_kernel<<<NB_MOL, 512, CHO_SHMEM>>>(feats, w, tc, out);
}

// round 17
// speedup vs baseline: 1.2365x; 1.2365x over previous
#include <cuda_runtime.h>
#include <math.h>

#define NB_MOL 128
#define NA 512
#define NF 64
#define CO 14.399645478425668f
#define SQRT_PI 1.7724538509055159f
#define PS 480

typedef unsigned long long u64;

// ---------------- scratch (device globals; no allocation allowed) ----------
__device__ float g_C[(size_t)NB_MOL * NA * NA];   // matrix / Cholesky factor (lower)

// ---------------- packed fp32x2 helpers (sm_103a FFMA2 path) ---------------
__device__ __forceinline__ void ffma2(u64& acc, u64 a, u64 b) {
    asm("fma.rn.f32x2 %0, %1, %2, %0;" : "+l"(acc) : "l"(a), "l"(b));
}
__device__ __forceinline__ u64 fmul2(u64 a, u64 b) {
    u64 r; asm("mul.rn.f32x2 %0, %1, %2;" : "=l"(r) : "l"(a), "l"(b)); return r;
}
__device__ __forceinline__ u64 fadd2(u64 a, u64 b) {
    u64 r; asm("add.rn.f32x2 %0, %1, %2;" : "=l"(r) : "l"(a), "l"(b)); return r;
}
__device__ __forceinline__ u64 splat2(float x) {
    u64 r; asm("mov.b64 %0, {%1, %1};" : "=l"(r) : "f"(x)); return r;
}
__device__ __forceinline__ u64 nsplat2(float x) {
    float nx = -x;
    u64 r; asm("mov.b64 %0, {%1, %1};" : "=l"(r) : "f"(nx)); return r;
}
__device__ __forceinline__ u64 pack2(float lo, float hi) {
    u64 r; asm("mov.b64 %0, {%1, %2};" : "=l"(r) : "f"(lo), "f"(hi)); return r;
}
__device__ __forceinline__ void unpack2(u64 v, float& lo, float& hi) {
    asm("mov.b64 {%0, %1}, %2;" : "=f"(lo), "=f"(hi) : "l"(v));
}

// ---------------- build C, LOWER TRIANGLE ONLY (pair table + erf sat) ------
__global__ void __launch_bounds__(256) build_kernel(const float* __restrict__ pos,
                                                    const int*   __restrict__ atype,
                                                    const float* __restrict__ hard,
                                                    const float* __restrict__ sigma) {
    __shared__ float sx[NA], sy[NA], sz[NA], sdg[NA];
    __shared__ int   st[NA];
    __shared__ float prg[16], prg2[16];
    int m   = blockIdx.y;
    int rb  = blockIdx.x * 32;
    int tid = threadIdx.x;
    for (int i = tid; i < NA; i += 256) {
        int g = m * NA + i;
        sx[i] = pos[3 * g];  sy[i] = pos[3 * g + 1];  sz[i] = pos[3 * g + 2];
        int sp = atype[g];
        st[i] = sp;
        float sg = sigma[sp];
        sdg[i] = hard[sp] * hard[sp] + CO / (SQRT_PI * sg);
    }
    if (tid < 16) {
        float sa = sigma[tid >> 2], sb = sigma[tid & 3];
        float rg = rsqrtf(2.f * (sa * sa + sb * sb));
        prg[tid]  = rg;
        prg2[tid] = rg * rg;
    }
    __syncthreads();
    float* C = g_C + (size_t)m * NA * NA;
    int ncol = rb + 32;
    for (int il = 0; il < 32; ++il) {
        int i = rb + il;
        float xi = sx[i], yi = sy[i], zi = sz[i];
        int   ti4 = st[i] * 4;
        for (int j = tid; j < ncol; j += 256) {
            float val;
            if (j == i) {
                val = sdg[i];
            } else {
                float dx = xi - sx[j], dy = yi - sy[j], dz = zi - sz[j];
                float d2 = dx * dx + dy * dy + dz * dz;
                float rd = rsqrtf(d2);
                int   pi = ti4 + st[j];
                float t2 = d2 * prg2[pi];
                if (t2 > 16.0f)
                    val = CO * rd;                              // erf saturated to 1
                else
                    val = CO * erff(d2 * rd * prg[pi]) * rd;
            }
            C[(size_t)i * NA + j] = val;
        }
    }
}

// ---------------- warp0-collective 32x32 Cholesky in shared ----------------
// (R14 structure; pivot via rsqrtf — removes divide + IEEE sqrt from chain)
__device__ __forceinline__ void factor32(float* D, float* inv, int lane) {
    for (int k = 0; k < 32; ++k) {
        if (lane == k) {
            float x  = D[k * 33 + k];
            float iv = rsqrtf(x);
            D[k * 33 + k] = x * iv;
            inv[k] = iv;
        }
        __syncwarp();
        if (lane > k) D[lane * 33 + k] *= inv[k];
        __syncwarp();
        if (lane > k) {
            float lik = D[lane * 33 + k];
            for (int j = k + 1; j <= lane; ++j)
                D[lane * 33 + j] -= lik * D[j * 33 + k];
        }
        __syncwarp();
    }
}

// ------- fused: chi + paired-panel Cholesky + fwd/bwd solve + outputs ------
// shared layout (float offsets)
#define SH_PT0    0                      // [32][PS] panel of even sub-block
#define SH_PT1    (32 * PS)              // [32][PS] panel of odd  sub-block
#define SH_D      (2 * 32 * PS)          // [32][33] diag block
#define SH_DT     (SH_D + 32 * 33)       // [32][34] transposed diag (u64-aligned)
#define SH_INV    (SH_DT + 32 * 34)      // [32]
#define SH_INVP2  (SH_INV + 32)          // [32] u64 pairs  (even float offset)
#define SH_INVALL (SH_INVP2 + 64)        // [512]
#define SH_BP     (SH_INVALL + 512)      // [512] u64 pairs (even float offset)
#define SH_CHI    (SH_BP + 1024)         // [512]
#define SH_RED    (SH_CHI + 512)         // [64]
#define SH_LAM    (SH_RED + 64)
#define CHO_SHMEM ((SH_LAM + 4) * 4)

extern __shared__ float cho_sh[];

__global__ void __launch_bounds__(512) fact_solve_kernel(const float* __restrict__ feats,
                                                         const float* __restrict__ wv,
                                                         const float* __restrict__ tc,
                                                         float* __restrict__ out) {
    float* s_Pt0    = cho_sh + SH_PT0;
    float* s_Pt1    = cho_sh + SH_PT1;
    float* s_D      = cho_sh + SH_D;
    float* s_DT     = cho_sh + SH_DT;
    float* s_inv    = cho_sh + SH_INV;
    u64*   s_invp2  = (u64*)(cho_sh + SH_INVP2);
    float* s_invall = cho_sh + SH_INVALL;
    u64*   s_bp     = (u64*)(cho_sh + SH_BP);
    float* s_chi    = cho_sh + SH_CHI;
    float* s_red    = cho_sh + SH_RED;
    float* s_lam    = cho_sh + SH_LAM;

    int m    = blockIdx.x;
    float* C = g_C + (size_t)m * NA * NA;
    int tid = threadIdx.x, lane = tid & 31, wid = tid >> 5;

    // ---- prologue: chi = feats @ w (per-warp shuffle reduce) ----
    {
        float w0 = wv[lane], w1 = wv[lane + 32];
        for (int a = wid; a < NA; a += 16) {
            const float* fr = feats + (size_t)(m * NA + a) * NF;
            float v = fr[lane] * w0 + fr[lane + 32] * w1;
#pragma unroll
            for (int off = 16; off; off >>= 1) v += __shfl_down_sync(0xffffffffu, v, off);
            if (lane == 0) s_chi[a] = v;
        }
    }
    __syncthreads();
    // rhs pairs: (b0, b1) = (-chi, 1)
    s_bp[tid] = pack2(-s_chi[tid], 1.0f);
    __syncthreads();

    // =================== factorization + forward substitution ==============
    for (int kb = 0; kb < NA / 32; ++kb) {
        int k0 = kb * 32;
        int M  = NA - k0 - 32;
        bool even = ((kb & 1) == 0);
        float* s_P = even ? s_Pt0 : s_Pt1;

        // ---- A: load diag block (all warps) ----
        for (int t = tid; t < 1024; t += 512) {
            int i = t >> 5, j = t & 31;
            s_D[i * 33 + j] = C[(size_t)(k0 + i) * NA + k0 + j];
        }
        __syncthreads();

        // ---- B: warp0 factors diag (+transpose); threads 32.. prefetch ----
        u64 ap[16];
        int r = tid - 32;
        bool havrow = (tid >= 32) && (r < M);
        if (wid == 0) {
            factor32(s_D, s_inv, lane);
            s_invall[k0 + lane] = s_inv[lane];
            s_invp2[lane] = (lane & 1) ? pack2(1.0f, s_inv[lane])
                                       : pack2(s_inv[lane], 1.0f);
            for (int e = lane; e < 1024; e += 32) {
                int i = e >> 5, j = e & 31;
                s_DT[j * 34 + i] = s_D[i * 33 + j];     // s_DT[t][j] = D[j][t]
            }
        } else if (havrow) {
            const double2* rp = (const double2*)(C + (size_t)(k0 + 32 + r) * NA + k0);
#pragma unroll
            for (int c = 0; c < 8; ++c) {
                double2 v = rp[c];
                ap[2 * c]     = __double_as_longlong(v.x);
                ap[2 * c + 1] = __double_as_longlong(v.y);
            }
        }
        __syncthreads();

        // ---- C: warp0 writes diag back; panel threads do paired trsm ----
        if (wid == 0) {
#pragma unroll
            for (int jc = 0; jc < 8; ++jc) {
                float4 v = make_float4(s_D[lane * 33 + 4 * jc],     s_D[lane * 33 + 4 * jc + 1],
                                       s_D[lane * 33 + 4 * jc + 2], s_D[lane * 33 + 4 * jc + 3]);
                *(float4*)(C + (size_t)(k0 + lane) * NA + k0 + 4 * jc) = v;
            }
        } else if (havrow) {
#pragma unroll
            for (int t = 0; t < 32; ++t) {
                int tp = t >> 1;
                ap[tp] = fmul2(ap[tp], s_invp2[t]);           // scale element t only
                float xlo, xhi;
                unpack2(ap[tp], xlo, xhi);
                float xv = (t & 1) ? xhi : xlo;
                if ((t & 1) == 0) {                            // partner j = t+1 in same pair
                    u64 p = *(const u64*)(s_DT + t * 34 + t);  // (D[t][t], D[t+1][t])
                    ffma2(ap[tp], pack2(0.0f, -xv), p);
                }
                u64 nx = nsplat2(xv);
#pragma unroll
                for (int jp = tp + 1; jp < 16; ++jp)
                    ffma2(ap[jp], nx, *(const u64*)(s_DT + t * 34 + 2 * jp));
            }
            double2* wp = (double2*)(C + (size_t)(k0 + 32 + r) * NA + k0);
#pragma unroll
            for (int c = 0; c < 8; ++c)
                wp[c] = make_double2(__longlong_as_double(ap[2 * c]),
                                     __longlong_as_double(ap[2 * c + 1]));
#pragma unroll
            for (int tp = 0; tp < 16; ++tp) {
                float lo, hi;
                unpack2(ap[tp], lo, hi);
                s_P[(2 * tp) * PS + r]     = lo;               // transposed panel
                s_P[(2 * tp + 1) * PS + r] = hi;
            }
        }
        __syncthreads();

        // ---- D: warp0 = forward solver; warps 1-15 = SYRK/skinny ----
        if (wid == 0) {
            // z-block solve: L11 z = b (both RHS packed)
            u64 av = s_bp[k0 + lane];
            for (int t = 0; t < 32; ++t) {
                u64 vt = __shfl_sync(0xffffffffu, av, t);
                u64 v  = fmul2(vt, splat2(s_inv[t]));
                if (lane == t) s_bp[k0 + t] = v;
                float l = s_D[lane * 33 + t];
                if (lane > t) ffma2(av, nsplat2(l), v);
            }
            __syncwarp();
            // trailing b -= L21 * z (panel in shared)
            for (int rr = lane; rr < M; rr += 32) {
                u64 bp = s_bp[k0 + 32 + rr];
#pragma unroll 8
                for (int t = 0; t < 32; ++t)
                    ffma2(bp, nsplat2(s_P[t * PS + rr]), s_bp[k0 + t]);
                s_bp[k0 + 32 + rr] = bp;
            }
        } else if (M > 0) {
            if (even) {
                // skinny update: next 32-col strip only (rank 32); static map
                int bi = wid - 1;
                if (bi * 32 < M) {
                    int rr = bi * 32 + lane;
                    u64 acc[16];
#pragma unroll
                    for (int c = 0; c < 16; ++c) acc[c] = 0ull;
#pragma unroll 8
                    for (int t = 0; t < 32; ++t) {
                        u64 na = nsplat2(s_P[t * PS + rr]);
                        const double2* pp = (const double2*)(s_P + t * PS);
#pragma unroll
                        for (int c = 0; c < 8; ++c) {
                            double2 p = pp[c];
                            ffma2(acc[2 * c],     na, __double_as_longlong(p.x));
                            ffma2(acc[2 * c + 1], na, __double_as_longlong(p.y));
                        }
                    }
                    double2* cp = (double2*)(C + (size_t)(k0 + 32 + rr) * NA + k0 + 32);
#pragma unroll
                    for (int c = 0; c < 8; ++c) {
                        double2 v = cp[c];
                        v.x = __longlong_as_double(fadd2(__double_as_longlong(v.x), acc[2 * c]));
                        v.y = __longlong_as_double(fadd2(__double_as_longlong(v.y), acc[2 * c + 1]));
                        cp[c] = v;
                    }
                }
            } else {
                // rank-64 trailing SYRK with both panels (64x32 tiles)
                int wslot = wid - 1;
                int RT = (M + 63) >> 6;
                int CT = M >> 5;
                int cnt = 0;
                for (int bi = 0; bi < RT; ++bi) {
                    int bjmax = min(2 * bi + 1, CT - 1);
                    for (int bj = 0; bj <= bjmax; ++bj) {
                        if (cnt == wslot) {
                            int r1 = bi * 64 + lane, r2 = r1 + 32;
                            int cb = bj * 32;
                            bool v1 = r1 < M, v2 = r2 < M;
                            u64 acc0[16], acc1[16];
#pragma unroll
                            for (int c = 0; c < 16; ++c) { acc0[c] = 0ull; acc1[c] = 0ull; }
                            // panel 1 (current odd block)
#pragma unroll 8
                            for (int t = 0; t < 32; ++t) {
                                float a0 = v1 ? s_Pt1[t * PS + r1] : 0.f;
                                float a1 = v2 ? s_Pt1[t * PS + r2] : 0.f;
                                u64 na0 = nsplat2(a0), na1 = nsplat2(a1);
                                const double2* pp = (const double2*)(s_Pt1 + t * PS + cb);
#pragma unroll
                                for (int c = 0; c < 8; ++c) {
                                    double2 p = pp[c];
                                    u64 pl = __double_as_longlong(p.x);
                                    u64 ph = __double_as_longlong(p.y);
                                    ffma2(acc0[2 * c],     na0, pl);
                                    ffma2(acc0[2 * c + 1], na0, ph);
                                    ffma2(acc1[2 * c],     na1, pl);
                                    ffma2(acc1[2 * c + 1], na1, ph);
                                }
                            }
                            // panel 0 (previous even block; rows shifted by 32)
#pragma unroll 8
                            for (int t = 0; t < 32; ++t) {
                                float a0 = v1 ? s_Pt0[t * PS + r1 + 32] : 0.f;
                                float a1 = v2 ? s_Pt0[t * PS + r2 + 32] : 0.f;
                                u64 na0 = nsplat2(a0), na1 = nsplat2(a1);
                                const double2* pp = (const double2*)(s_Pt0 + t * PS + cb + 32);
#pragma unroll
                                for (int c = 0; c < 8; ++c) {
                                    double2 p = pp[c];
                                    u64 pl = __double_as_longlong(p.x);
                                    u64 ph = __double_as_longlong(p.y);
                                    ffma2(acc0[2 * c],     na0, pl);
                                    ffma2(acc0[2 * c + 1], na0, ph);
                                    ffma2(acc1[2 * c],     na1, pl);
                                    ffma2(acc1[2 * c + 1], na1, ph);
                                }
                            }
                            if (v1) {
                                double2* cp = (double2*)(C + (size_t)(k0 + 32 + r1) * NA + k0 + 32 + cb);
#pragma unroll
                                for (int c = 0; c < 8; ++c) {
                                    double2 v = cp[c];
                                    v.x = __longlong_as_double(fadd2(__double_as_longlong(v.x), acc0[2 * c]));
                                    v.y = __longlong_as_double(fadd2(__double_as_longlong(v.y), acc0[2 * c + 1]));
                                    cp[c] = v;
                                }
                            }
                            if (v2) {
                                double2* cp = (double2*)(C + (size_t)(k0 + 32 + r2) * NA + k0 + 32 + cb);
#pragma unroll
                                for (int c = 0; c < 8; ++c) {
                                    double2 v = cp[c];
                                    v.x = __longlong_as_double(fadd2(__double_as_longlong(v.x), acc1[2 * c]));
                                    v.y = __longlong_as_double(fadd2(__double_as_longlong(v.y), acc1[2 * c + 1]));
                                    cp[c] = v;
                                }
                            }
                        }
                        if (++cnt == 15) cnt = 0;
                    }
                }
            }
        }
        __syncthreads();
    }

    // =================== backward: L^T y = z ================================
    for (int kb = NA / 32 - 1; kb >= 0; --kb) {
        int k0 = kb * 32;
        if (wid == 0) {
            for (int e = lane; e < 1024; e += 32) {
                int i = e >> 5, j = e & 31;
                s_D[i * 33 + j] = C[(size_t)(k0 + i) * NA + k0 + j];
            }
            __syncwarp();
            u64 av = s_bp[k0 + lane];
            for (int t = 31; t >= 0; --t) {
                u64 vt = __shfl_sync(0xffffffffu, av, t);
                u64 v  = fmul2(vt, splat2(s_invall[k0 + t]));
                if (lane == t) s_bp[k0 + t] = v;
                float l = s_D[t * 33 + lane];
                if (lane < t) ffma2(av, nsplat2(l), v);
            }
        }
        __syncthreads();
        for (int j = tid; j < k0; j += 512) {
            u64 bp = s_bp[j];
#pragma unroll
            for (int t = 0; t < 32; ++t)
                ffma2(bp, nsplat2(C[(size_t)(k0 + t) * NA + j]), s_bp[k0 + t]);
            s_bp[j] = bp;
        }
        __syncthreads();
    }

    // =================== lambda, q, energy ==================================
    float y0, y1;
    unpack2(s_bp[tid], y0, y1);
    float l0 = y0, l1 = y1;
#pragma unroll
    for (int off = 16; off; off >>= 1) {
        l0 += __shfl_down_sync(0xffffffffu, l0, off);
        l1 += __shfl_down_sync(0xffffffffu, l1, off);
    }
    if (lane == 0) { s_red[wid] = l0; s_red[32 + wid] = l1; }
    __syncthreads();
    if (tid == 0) {
        float S1 = 0.f, S2 = 0.f;
        for (int w = 0; w < 16; ++w) { S1 += s_red[w]; S2 += s_red[32 + w]; }
        *s_lam = (S1 - tc[m]) / S2;
    }
    __syncthreads();
    float lam = *s_lam;

    float q = y0 - lam * y1;
    out[NB_MOL + m * NA + tid] = q;

    // e = 0.5 * (chi.q - lam * Q)   [exact KKT identity]
    float ep = s_chi[tid] * q;
#pragma unroll
    for (int off = 16; off; off >>= 1) ep += __shfl_down_sync(0xffffffffu, ep, off);
    if (lane == 0) s_red[wid] = ep;
    __syncthreads();
    if (tid == 0) {
        float s = 0.f;
        for (int w = 0; w < 16; ++w) s += s_red[w];
        out[m] = 0.5f * (s - lam * tc[m]);
    }
}

// ---------------- launch ----------------------------------------------------
extern "C" void kernel_launch(void* const* d_in, const int* in_sizes, int n_in,
                              void* d_out, int out_size) {
    const float* feats = (const float*)d_in[0];   // (N, 64)
    const float* pos   = (const float*)d_in[1];   // (N, 3)
    const int*   atype = (const int*)  d_in[2];   // (N,)
    const float* tc    = (const float*)d_in[3];   // (B, 1)
    const float* w     = (const float*)d_in[4];   // (64, 1)
    const float* hard  = (const float*)d_in[5];   // (4,)
    const float* sigma = (const float*)d_in[6];   // (4,)
    float* out = (float*)d_out;                   // [B e | N q]

    (void)in_sizes; (void)n_in; (void)out_size;

    build_kernel<<<dim3(16, NB_MOL), 256>>>(pos, atype, hard, sigma);
    cudaFuncSetAttribute(fact_solve_kernel, cudaFuncAttributeMaxDynamicSharedMemorySize, CHO_SHMEM);
    fact_solve_kernel<<<NB_MOL, 512, CHO_SHMEM>>>(feats, w, tc, out);
}